// round 15
// baseline (speedup 1.0000x reference)
#include <cuda_runtime.h>

typedef unsigned int u32;
typedef unsigned long long u64;

// ---- packed f32x2 helpers (Blackwell sm_103a) ------------------------------
__device__ __forceinline__ u64 pack2(float lo, float hi) {
    u64 r; asm("mov.b64 %0, {%1, %2};" : "=l"(r) : "f"(lo), "f"(hi)); return r;
}
__device__ __forceinline__ void unpack2(u64 v, float& lo, float& hi) {
    asm("mov.b64 {%0, %1}, %2;" : "=f"(lo), "=f"(hi) : "l"(v));
}
__device__ __forceinline__ void fma2(u64& d, u64 a, u64 b, u64 c) {
    asm("fma.rn.f32x2 %0, %1, %2, %3;" : "=l"(d) : "l"(a), "l"(b), "l"(c));
}

#define H2C 2654435761u
#define H3C 805459861u

// Output columns split across WARPS (warp-uniform -> LDC stays uniform, the
// R8 failure mode is structurally avoided). Per-thread state halves ->
// 5 blocks/SM = 20 warps (vs 16) with per-warp critical path halved.
// Port split per warp-half: gemm1/3: 4 const + 4 smem col groups;
// gemm2: all const; gemm4: 2 const + 6 smem; gemm5 const.
#define OFF_S1 0
#define OFF_S2 2048
#define OFF_C1 3072
#define OFF_C2 5120
#define OFF_C3 9216
#define W_TOTAL 9408
__constant__ __align__(16) float CW[W_TOTAL];
__device__   __align__(16) float WPACK[W_TOTAL];

__global__ void pack_weights(const float* __restrict__ s1,
                             const float* __restrict__ s2,
                             const float* __restrict__ c1,
                             const float* __restrict__ c2,
                             const float* __restrict__ c3) {
    int t = blockIdx.x * 256 + threadIdx.x;
    if (t >= W_TOTAL) return;
    float v;
    if      (t < OFF_S2) v = s1[t - OFF_S1];
    else if (t < OFF_C1) v = s2[t - OFF_S2];
    else if (t < OFF_C2) v = c1[t - OFF_C1];
    else if (t < OFF_C3) v = c2[t - OFF_C2];
    else                 v = c3[t - OFF_C3];
    WPACK[t] = v;
}

// res = ceil(16 * s^l), s = float32(2^0.4) (rounded up) => 65/257/1025 at
// l=5/10/15. MAX_DIRECT = 2.
__device__ __forceinline__ void level_load(int l, float px, float py, float pz,
                                           const float* __restrict__ grids,
                                           float2* cc)
{
    const int RES_[16]  = {16,22,28,37,49,65,85,112,148,195,257,338,446,589,777,1025};
    const u32 SZ_[16]   = {4096u,10648u,21952u,50656u,117656u,274632u,
                           524288u,524288u,524288u,524288u,524288u,
                           524288u,524288u,524288u,524288u,524288u};
    const int R = RES_[l];
    const u32 S = SZ_[l];
    const float Rf = (float)R;
    int ix = (int)floorf(px * Rf);
    int iy = (int)floorf(py * Rf);
    int iz = (int)floorf(pz * Rf);

    u32 idx[8];
    if (l <= 2) {
        #pragma unroll
        for (int j = 0; j < 8; j++) {
            int cx = ix + ((j >> 2) & 1);
            int cy = iy + ((j >> 1) & 1);
            int cz = iz + (j & 1);
            idx[j] = (u32)(cz * (R * R) + cy * R + cx) % S;
        }
    } else {
        u32 hx0 = (u32)ix;           u32 hx1 = hx0 + 1u;
        u32 hy0 = (u32)iy * H2C;     u32 hy1 = hy0 + H2C;
        u32 hz0 = (u32)iz * H3C;     u32 hz1 = hz0 + H3C;
        #pragma unroll
        for (int j = 0; j < 8; j++) {
            u32 h = ((j & 4) ? hx1 : hx0) ^ ((j & 2) ? hy1 : hy0) ^ ((j & 1) ? hz1 : hz0);
            idx[j] = (l >= 6) ? (h & 524287u) : (h % S);
        }
    }

    const float2* g = (const float2*)grids + (size_t)l * 524288u;
    #pragma unroll
    for (int j = 0; j < 8; j++) cc[j] = __ldg(g + idx[j]);
}

__device__ __forceinline__ void level_lerp(int l, float px, float py, float pz,
                                           const float2* cc, float* e2)
{
    const int RES_[16] = {16,22,28,37,49,65,85,112,148,195,257,338,446,589,777,1025};
    const float Rf = (float)RES_[l];
    float u = px * Rf, v = py * Rf, w = pz * Rf;
    float fx = u - floorf(u), fy = v - floorf(v), fz = w - floorf(w);
    const float gx = 1.f - fx, gy = 1.f - fy, gz = 1.f - fz;
    float c00x = cc[0].x*gx + cc[4].x*fx, c00y = cc[0].y*gx + cc[4].y*fx;
    float c01x = cc[1].x*gx + cc[5].x*fx, c01y = cc[1].y*gx + cc[5].y*fx;
    float c10x = cc[2].x*gx + cc[6].x*fx, c10y = cc[2].y*gx + cc[6].y*fx;
    float c11x = cc[3].x*gx + cc[7].x*fx, c11y = cc[3].y*gx + cc[7].y*fx;
    float c0x = c00x*gy + c10x*fy, c0y = c00y*gy + c10y*fy;
    float c1x = c01x*gy + c11x*fy, c1y = c01y*gy + c11y*fy;
    // NOTE: replicates reference bug: c0*(1-fz) + c1*fy   (fy, not fz!)
    e2[0] = c0x*gz + c1x*fy;
    e2[1] = c0y*gz + c1y*fy;
}

// Gather 8 levels [L0, L0+8) with distance-1 pipelined loads (R13 pattern).
template<int L0>
__device__ __forceinline__ void gather8(float px, float py, float pz,
                                        const float* __restrict__ grids,
                                        float* enc16)
{
    float2 ccA[8], ccB[8];
    level_load(L0, px, py, pz, grids, ccA);
    #pragma unroll
    for (int l = L0; l < L0 + 8; l += 2) {
        level_load(l + 1, px, py, pz, grids, ccB);
        level_lerp(l, px, py, pz, ccA, enc16 + 2*(l - L0));
        if (l + 2 < L0 + 8) level_load(l + 2, px, py, pz, grids, ccA);
        level_lerp(l + 1, px, py, pz, ccB, enc16 + 2*(l + 1 - L0));
    }
}

__global__ void __launch_bounds__(128, 5) nerf_fused(
    const float* __restrict__ xin,     // (N,19)
    const float* __restrict__ grids,   // (16, 524288, 2)
    const float* __restrict__ gw_s1,   // (32,64)
    const float* __restrict__ gw_c1,   // (32,64)
    const float* __restrict__ gw_c2,   // (64,64)
    float* __restrict__ out,           // (N,4)
    int N)
{
    // BUF: activation exchange, chunk-major float4 [16 rows][64 points]:
    //   rows 0-7: enc (32 floats/pt); rows 8-15: ov partials; later rows 0-15: hc.
    __shared__ __align__(16) float4 BUF[16][64];
    // smem weight slices (per warp-half upper col groups):
    __shared__ __align__(16) ulonglong2 W1s[32 * 8];   // s1 cols 16-31 / 48-63
    __shared__ __align__(16) ulonglong2 W3s[32 * 8];   // c1 cols 16-31 / 48-63
    __shared__ __align__(16) ulonglong2 W4s[64 * 12];  // c2 cols 8-31 / 40-63
    __shared__ float sx[64 * 19];                      // staged xin (19 coprime 32)

    const int tid = threadIdx.x;
    {
        float* w1f = (float*)W1s;
        float* w3f = (float*)W3s;
        float* w4f = (float*)W4s;
        for (int t = tid; t < 1024; t += 128) {         // 32 rows x 32 floats
            int k = t >> 5, cf = t & 31;
            int col = (cf < 16) ? 16 + cf : 32 + cf;    // 16..31 / 48..63
            w1f[t] = gw_s1[k * 64 + col];
            w3f[t] = gw_c1[k * 64 + col];
        }
        for (int t = tid; t < 3072; t += 128) {         // 64 rows x 48 floats
            int k = t / 48, cf = t % 48;
            int col = (cf < 24) ? 8 + cf : 16 + cf;     // 8..31 / 40..63
            w4f[t] = gw_c2[k * 64 + col];
        }
        const int gbase = blockIdx.x * (64 * 19);
        const int lim   = N * 19;
        #pragma unroll
        for (int t = tid; t < 64 * 19; t += 128) {
            int g = gbase + t;
            sx[t] = (g < lim) ? xin[g] : 0.f;
        }
    }
    __syncthreads();

    const int lane    = tid & 31;
    const int wid     = tid >> 5;
    const int colHalf = wid >> 1;            // warps 0,1 -> cols 0-31; 2,3 -> 32-63
    const int pgrp    = wid & 1;
    const int pt      = pgrp * 32 + lane;    // point slot in block (0..63)
    const int i       = blockIdx.x * 64 + pt;
    const int base    = colHalf * 32;        // this warp's output col base

    const float px = sx[pt * 19 + 0];
    const float py = sx[pt * 19 + 1];
    const float pz = sx[pt * 19 + 2];

    // ---- phase A: gather, 8 levels per warp (split by colHalf) --------------
    {
        float enc16[16];
        if (colHalf == 0) gather8<0>(px, py, pz, grids, enc16);
        else              gather8<8>(px, py, pz, grids, enc16);
        #pragma unroll
        for (int c = 0; c < 4; c++)
            BUF[colHalf * 4 + c][pt] =
                make_float4(enc16[4*c], enc16[4*c+1], enc16[4*c+2], enc16[4*c+3]);
    }
    __syncthreads();   // #2: enc complete

    // ---- gemm1 (32x64): this warp computes h1 cols base..base+31 ------------
    // acc[q]: q<8 -> cols base+2q (const groups); q>=8 -> base+16+2(q-8) (smem).
    // col(q) = base + 2q uniformly.
    u64 acc[16];
    #pragma unroll
    for (int j = 0; j < 16; j++) acc[j] = 0ull;
    const ulonglong2* W1c = (const ulonglong2*)(CW + OFF_S1);

    #pragma unroll
    for (int jj = 0; jj < 8; jj++) {
        float4 e = BUF[jj][pt];
        float ek[4] = {e.x, e.y, e.z, e.w};
        #pragma unroll
        for (int t = 0; t < 4; t++) {
            int k = 4*jj + t;
            u64 a = pack2(ek[t], ek[t]);
            #pragma unroll
            for (int j = 0; j < 4; j++) {
                ulonglong2 w = W1c[k*16 + colHalf*8 + j];   // cols base+4j
                fma2(acc[2*j],   a, w.x, acc[2*j]);
                fma2(acc[2*j+1], a, w.y, acc[2*j+1]);
                ulonglong2 s = W1s[k*8 + colHalf*4 + j];    // cols base+16+4j
                fma2(acc[8+2*j],   a, s.x, acc[8+2*j]);
                fma2(acc[8+2*j+1], a, s.y, acc[8+2*j+1]);
            }
        }
    }

    // ---- relu(h1 half) folded into gemm2 partial (k-split), ALL const -------
    u64 ovacc[8];
    #pragma unroll
    for (int j = 0; j < 8; j++) ovacc[j] = 0ull;
    const ulonglong2* W2c = (const ulonglong2*)(CW + OFF_S2);

    #pragma unroll
    for (int q = 0; q < 16; q++) {
        float lo, hi; unpack2(acc[q], lo, hi);
        lo = fmaxf(lo, 0.f); hi = fmaxf(hi, 0.f);
        int m = base + 2*q;
        u64 alo = pack2(lo, lo), ahi = pack2(hi, hi);
        #pragma unroll
        for (int j = 0; j < 4; j++) {
            ulonglong2 w0 = W2c[m*4 + j];
            ulonglong2 w1 = W2c[(m+1)*4 + j];
            fma2(ovacc[2*j],   alo, w0.x, ovacc[2*j]);
            fma2(ovacc[2*j+1], alo, w0.y, ovacc[2*j+1]);
            fma2(ovacc[2*j],   ahi, w1.x, ovacc[2*j]);
            fma2(ovacc[2*j+1], ahi, w1.y, ovacc[2*j+1]);
        }
    }
    // exchange + reduce ov partials (rows 8-11: half0, rows 12-15: half1)
    #pragma unroll
    for (int j = 0; j < 4; j++) {
        float f0, f1, f2, f3;
        unpack2(ovacc[2*j],   f0, f1);
        unpack2(ovacc[2*j+1], f2, f3);
        BUF[8 + colHalf*4 + j][pt] = make_float4(f0, f1, f2, f3);
    }
    __syncthreads();   // #3: partials visible
    float ov[16];
    {
        int o = 8 + (1 - colHalf) * 4;
        #pragma unroll
        for (int j = 0; j < 4; j++) {
            float4 p = BUF[o + j][pt];
            float f0, f1, f2, f3;
            unpack2(ovacc[2*j],   f0, f1);
            unpack2(ovacc[2*j+1], f2, f3);
            ov[4*j]   = f0 + p.x;
            ov[4*j+1] = f1 + p.y;
            ov[4*j+2] = f2 + p.z;
            ov[4*j+3] = f3 + p.w;
        }
    }
    const float sigma = ov[0];
    __syncthreads();   // #4: ov reads done (rows 8-15 free for hc)

    // ---- gemm3 (32x64): full k, cols base..base+31 ---------------------------
    u64 acc3[16];
    #pragma unroll
    for (int j = 0; j < 16; j++) acc3[j] = 0ull;
    const ulonglong2* W3c = (const ulonglong2*)(CW + OFF_C1);

    #pragma unroll
    for (int k = 0; k < 32; k++) {
        float cik = (k < 16) ? sx[pt*19 + 3 + k] : ov[k - 16];
        u64 a = pack2(cik, cik);
        #pragma unroll
        for (int j = 0; j < 4; j++) {
            ulonglong2 w = W3c[k*16 + colHalf*8 + j];
            fma2(acc3[2*j],   a, w.x, acc3[2*j]);
            fma2(acc3[2*j+1], a, w.y, acc3[2*j+1]);
            ulonglong2 s = W3s[k*8 + colHalf*4 + j];
            fma2(acc3[8+2*j],   a, s.x, acc3[8+2*j]);
            fma2(acc3[8+2*j+1], a, s.y, acc3[8+2*j+1]);
        }
    }
    // relu -> hc exchange: thread's cols base..base+31 -> chunks colHalf*8+u
    #pragma unroll
    for (int u = 0; u < 8; u++) {
        float f0, f1, f2, f3;
        unpack2(acc3[2*u],   f0, f1);
        unpack2(acc3[2*u+1], f2, f3);
        BUF[colHalf*8 + u][pt] =
            make_float4(fmaxf(f0, 0.f), fmaxf(f1, 0.f), fmaxf(f2, 0.f), fmaxf(f3, 0.f));
    }
    __syncthreads();   // #5: hc complete

    // ---- gemm4 (64x64): full k from BUF, cols base..base+31 ------------------
    // a4[q]: q<4 const (cols base+2q); q>=4 smem (base+8+2(q-4)); col(q)=base+2q.
    u64 a4[16];
    #pragma unroll
    for (int j = 0; j < 16; j++) a4[j] = 0ull;
    const ulonglong2* W4c = (const ulonglong2*)(CW + OFF_C2);

    #pragma unroll
    for (int jj = 0; jj < 16; jj++) {
        float4 h = BUF[jj][pt];
        float hk[4] = {h.x, h.y, h.z, h.w};
        #pragma unroll
        for (int t = 0; t < 4; t++) {
            int k = 4*jj + t;
            u64 a = pack2(hk[t], hk[t]);
            #pragma unroll
            for (int j = 0; j < 2; j++) {
                ulonglong2 w = W4c[k*16 + colHalf*8 + j];   // cols base+4j
                fma2(a4[2*j],   a, w.x, a4[2*j]);
                fma2(a4[2*j+1], a, w.y, a4[2*j+1]);
            }
            #pragma unroll
            for (int j = 0; j < 6; j++) {
                ulonglong2 s = W4s[k*12 + colHalf*6 + j];   // cols base+8+4j
                fma2(a4[4+2*j],   a, s.x, a4[4+2*j]);
                fma2(a4[4+2*j+1], a, s.y, a4[4+2*j+1]);
            }
        }
    }

    // ---- relu + gemm5 partial (k-split over cols), const ---------------------
    float c0 = 0.f, c1 = 0.f, c2 = 0.f;
    #pragma unroll
    for (int q = 0; q < 16; q++) {
        float lo, hi; unpack2(a4[q], lo, hi);
        lo = fmaxf(lo, 0.f); hi = fmaxf(hi, 0.f);
        int c = base + 2*q;
        c0 += lo * CW[OFF_C3 + c*3 + 0] + hi * CW[OFF_C3 + (c+1)*3 + 0];
        c1 += lo * CW[OFF_C3 + c*3 + 1] + hi * CW[OFF_C3 + (c+1)*3 + 1];
        c2 += lo * CW[OFF_C3 + c*3 + 2] + hi * CW[OFF_C3 + (c+1)*3 + 2];
    }
    __syncthreads();   // #6: gemm4 hc reads done (row 0 free)
    if (colHalf == 1)
        BUF[0][pt] = make_float4(c0, c1, c2, 0.f);
    __syncthreads();   // #7: partial visible
    if (colHalf == 0 && i < N) {
        float4 p = BUF[0][pt];
        c0 += p.x; c1 += p.y; c2 += p.z;
        float4 r;
        r.x = 1.f / (1.f + expf(-c0));
        r.y = 1.f / (1.f + expf(-c1));
        r.z = 1.f / (1.f + expf(-c2));
        r.w = sigma;
        ((float4*)out)[i] = r;
    }
}

extern "C" void kernel_launch(void* const* d_in, const int* in_sizes, int n_in,
                              void* d_out, int out_size) {
    const float* x     = (const float*)d_in[0];
    const float* grids = (const float*)d_in[1];
    const float* ws1   = (const float*)d_in[2];
    const float* ws2   = (const float*)d_in[3];
    const float* wc1   = (const float*)d_in[4];
    const float* wc2   = (const float*)d_in[5];
    const float* wc3   = (const float*)d_in[6];
    float* out = (float*)d_out;

    // pack all weights into one device buffer, then ONE memcpy node to const.
    pack_weights<<<(W_TOTAL + 255) / 256, 256>>>(ws1, ws2, wc1, wc2, wc3);
    void* wpack_ptr = nullptr;
    cudaGetSymbolAddress(&wpack_ptr, WPACK);
    cudaMemcpyToSymbolAsync(CW, wpack_ptr, W_TOTAL * sizeof(float), 0,
                            cudaMemcpyDeviceToDevice, 0);

    const int N = in_sizes[0] / 19;
    const int blocks = (N + 63) / 64;   // 64 points per 128-thread block
    nerf_fused<<<blocks, 128>>>(x, grids, ws1, wc1, wc2, out, N);
}

// round 16
// speedup vs baseline: 3.0264x; 3.0264x over previous
#include <cuda_runtime.h>

typedef unsigned int u32;
typedef unsigned long long u64;

// ---- packed f32x2 helpers (Blackwell sm_103a) ------------------------------
__device__ __forceinline__ u64 pack2(float lo, float hi) {
    u64 r; asm("mov.b64 %0, {%1, %2};" : "=l"(r) : "f"(lo), "f"(hi)); return r;
}
__device__ __forceinline__ void unpack2(u64 v, float& lo, float& hi) {
    asm("mov.b64 {%0, %1}, %2;" : "=f"(lo), "=f"(hi) : "l"(v));
}
__device__ __forceinline__ void fma2(u64& d, u64 a, u64 b, u64 c) {
    asm("fma.rn.f32x2 %0, %1, %2, %3;" : "=l"(d) : "l"(a), "l"(b), "l"(c));
}

#define H2C 2654435761u
#define H3C 805459861u

// R14 port split (validated best):
//   gemm1/3: 8 const + 8 smem col-groups (cols 0..31 / 32..63)
//   gemm2:   ALL const;  gemm4: 4 const + 12 smem (cols 0..15 / 16..63)
//   gemm5:   const
// HARD RULE (R8+R15): every LDC index must be compile-time/loop-index only —
// NO tid-derived terms, or ptxas demotes to serialized per-thread LDC.
#define OFF_S1 0
#define OFF_S2 2048
#define OFF_C1 3072
#define OFF_C2 5120
#define OFF_C3 9216
#define W_TOTAL 9408
__constant__ __align__(16) float CW[W_TOTAL];
__device__   __align__(16) float WPACK[W_TOTAL];

__global__ void pack_weights(const float* __restrict__ s1,
                             const float* __restrict__ s2,
                             const float* __restrict__ c1,
                             const float* __restrict__ c2,
                             const float* __restrict__ c3) {
    int t = blockIdx.x * 256 + threadIdx.x;
    if (t >= W_TOTAL) return;
    float v;
    if      (t < OFF_S2) v = s1[t - OFF_S1];
    else if (t < OFF_C1) v = s2[t - OFF_S2];
    else if (t < OFF_C2) v = c1[t - OFF_C1];
    else if (t < OFF_C3) v = c2[t - OFF_C2];
    else                 v = c3[t - OFF_C3];
    WPACK[t] = v;
}

// res = ceil(16 * s^l), s = float32(2^0.4) (rounded up) => 65/257/1025 at
// l=5/10/15. MAX_DIRECT = 2.
// Computes indices AND fractions once (R16: de-duplicated position math).
__device__ __forceinline__ void level_load(int l, float px, float py, float pz,
                                           const float* __restrict__ grids,
                                           float2* cc, float* fr)
{
    const int RES_[16]  = {16,22,28,37,49,65,85,112,148,195,257,338,446,589,777,1025};
    const u32 SZ_[16]   = {4096u,10648u,21952u,50656u,117656u,274632u,
                           524288u,524288u,524288u,524288u,524288u,
                           524288u,524288u,524288u,524288u,524288u};
    const int R = RES_[l];
    const u32 S = SZ_[l];
    const float Rf = (float)R;
    float u = px * Rf, v = py * Rf, w = pz * Rf;
    float fu = floorf(u), fv = floorf(v), fw = floorf(w);
    fr[0] = u - fu; fr[1] = v - fv; fr[2] = w - fw;
    int ix = (int)fu, iy = (int)fv, iz = (int)fw;

    u32 idx[8];
    if (l <= 2) {
        #pragma unroll
        for (int j = 0; j < 8; j++) {
            int cx = ix + ((j >> 2) & 1);
            int cy = iy + ((j >> 1) & 1);
            int cz = iz + (j & 1);
            idx[j] = (u32)(cz * (R * R) + cy * R + cx) % S;
        }
    } else {
        u32 hx0 = (u32)ix;           u32 hx1 = hx0 + 1u;
        u32 hy0 = (u32)iy * H2C;     u32 hy1 = hy0 + H2C;
        u32 hz0 = (u32)iz * H3C;     u32 hz1 = hz0 + H3C;
        #pragma unroll
        for (int j = 0; j < 8; j++) {
            u32 h = ((j & 4) ? hx1 : hx0) ^ ((j & 2) ? hy1 : hy0) ^ ((j & 1) ? hz1 : hz0);
            idx[j] = (l >= 6) ? (h & 524287u) : (h % S);
        }
    }

    const float2* g = (const float2*)grids + (size_t)l * 524288u;
    #pragma unroll
    for (int j = 0; j < 8; j++) cc[j] = __ldg(g + idx[j]);
}

__global__ void __launch_bounds__(128, 4) nerf_fused(
    const float* __restrict__ xin,     // (N,19)
    const float* __restrict__ grids,   // (16, 524288, 2)
    const float* __restrict__ gw_s1,   // (32,64)
    const float* __restrict__ gw_s2,   // unused (gemm2 all const)
    const float* __restrict__ gw_c1,   // (32,64)
    const float* __restrict__ gw_c2,   // (64,64)
    float* __restrict__ out,           // (N,4)
    int N)
{
    __shared__ __align__(16) ulonglong2 W1s[32 * 8];   // s1 cols 32..63
    __shared__ __align__(16) ulonglong2 W3s[32 * 8];   // c1 cols 32..63
    __shared__ __align__(16) ulonglong2 W4s[64 * 12];  // c2 cols 16..63
    __shared__ float sx[128 * 19];                     // staged xin

    const int tid = threadIdx.x;
    {
        float* w1f = (float*)W1s;
        float* w3f = (float*)W3s;
        float* w4f = (float*)W4s;
        for (int t = tid; t < 1024; t += 128) {
            int r = t >> 5, c = t & 31;
            w1f[t] = gw_s1[r * 64 + 32 + c];
            w3f[t] = gw_c1[r * 64 + 32 + c];
        }
        for (int t = tid; t < 3072; t += 128) {        // 64 rows x 48 cols (16..63)
            int r = t / 48, c = t % 48;
            w4f[t] = gw_c2[r * 64 + 16 + c];
        }
        const int base = blockIdx.x * (128 * 19);
        const int lim  = N * 19;
        #pragma unroll
        for (int t = tid; t < 128 * 19; t += 128) {
            int g = base + t;
            sx[t] = (g < lim) ? xin[g] : 0.f;
        }
    }
    __syncthreads();

    const int i = blockIdx.x * 128 + tid;
    if (i >= N) return;

    const float px = sx[tid * 19 + 0];
    const float py = sx[tid * 19 + 1];
    const float pz = sx[tid * 19 + 2];

    // ---- phase A: gather FUSED with gemm1, distance-1 pipelined loads -------
    u64 acc[32];
    #pragma unroll
    for (int j = 0; j < 32; j++) acc[j] = 0ull;
    const ulonglong2* W1c = (const ulonglong2*)(CW + OFF_S1);

    float2 ccA[8], ccB[8];
    float frA[3], frB[3];
    level_load(0, px, py, pz, grids, ccA, frA);

    #pragma unroll
    for (int l = 0; l < 16; l += 2) {
        level_load(l + 1, px, py, pz, grids, ccB, frB);

        #pragma unroll
        for (int half = 0; half < 2; half++) {
            const int lv = l + half;
            const float2* cc = half ? ccB : ccA;
            const float*  fr = half ? frB : frA;
            const float fx = fr[0], fy = fr[1], fz = fr[2];

            if (half == 1 && l + 2 < 16)
                level_load(l + 2, px, py, pz, grids, ccA, frA);

            const float gx = 1.f - fx, gy = 1.f - fy, gz = 1.f - fz;
            float c00x = cc[0].x*gx + cc[4].x*fx, c00y = cc[0].y*gx + cc[4].y*fx;
            float c01x = cc[1].x*gx + cc[5].x*fx, c01y = cc[1].y*gx + cc[5].y*fx;
            float c10x = cc[2].x*gx + cc[6].x*fx, c10y = cc[2].y*gx + cc[6].y*fx;
            float c11x = cc[3].x*gx + cc[7].x*fx, c11y = cc[3].y*gx + cc[7].y*fx;
            float c0x = c00x*gy + c10x*fy, c0y = c00y*gy + c10y*fy;
            float c1x = c01x*gy + c11x*fy, c1y = c01y*gy + c11y*fy;
            // NOTE: replicates reference bug: c0*(1-fz) + c1*fy  (fy, not fz!)
            float fex = c0x*gz + c1x*fy;
            float fey = c0y*gz + c1y*fy;

            u64 a0 = pack2(fex, fex);
            u64 a1 = pack2(fey, fey);
            #pragma unroll
            for (int j = 0; j < 8; j++) {
                ulonglong2 w0 = W1c[(2*lv)   * 16 + j];    // cols 4j..4j+3
                ulonglong2 w1 = W1c[(2*lv+1) * 16 + j];
                fma2(acc[2*j],   a0, w0.x, acc[2*j]);
                fma2(acc[2*j+1], a0, w0.y, acc[2*j+1]);
                fma2(acc[2*j],   a1, w1.x, acc[2*j]);
                fma2(acc[2*j+1], a1, w1.y, acc[2*j+1]);
                ulonglong2 s0 = W1s[(2*lv)   * 8 + j];     // cols 32+4j..+3
                ulonglong2 s1v = W1s[(2*lv+1) * 8 + j];
                fma2(acc[16+2*j],   a0, s0.x,  acc[16+2*j]);
                fma2(acc[16+2*j+1], a0, s0.y,  acc[16+2*j+1]);
                fma2(acc[16+2*j],   a1, s1v.x, acc[16+2*j]);
                fma2(acc[16+2*j+1], a1, s1v.y, acc[16+2*j+1]);
            }
        }
    }

    // ---- relu(h1) folded into gemm2 (64x16), ALL const ----------------------
    u64 ovacc[8];
    #pragma unroll
    for (int j = 0; j < 8; j++) ovacc[j] = 0ull;
    const ulonglong2* W2c = (const ulonglong2*)(CW + OFF_S2);

    #pragma unroll
    for (int q = 0; q < 32; q++) {
        float lo, hi; unpack2(acc[q], lo, hi);
        lo = fmaxf(lo, 0.f); hi = fmaxf(hi, 0.f);
        int m = 2*q;
        u64 alo = pack2(lo, lo), ahi = pack2(hi, hi);
        #pragma unroll
        for (int j = 0; j < 4; j++) {
            ulonglong2 w0 = W2c[m*4 + j];
            ulonglong2 w1 = W2c[(m+1)*4 + j];
            fma2(ovacc[2*j],   alo, w0.x, ovacc[2*j]);
            fma2(ovacc[2*j+1], alo, w0.y, ovacc[2*j+1]);
            fma2(ovacc[2*j],   ahi, w1.x, ovacc[2*j]);
            fma2(ovacc[2*j+1], ahi, w1.y, ovacc[2*j+1]);
        }
    }
    float ov[16];
    #pragma unroll
    for (int j = 0; j < 8; j++) unpack2(ovacc[j], ov[2*j], ov[2*j+1]);
    const float sigma = ov[0];

    // ---- gemm3 (32x64), dual-port -------------------------------------------
    u64 acc3[32];
    #pragma unroll
    for (int j = 0; j < 32; j++) acc3[j] = 0ull;
    const ulonglong2* W3c = (const ulonglong2*)(CW + OFF_C1);
    const ulonglong2* W4c = (const ulonglong2*)(CW + OFF_C2);

    #pragma unroll
    for (int k = 0; k < 32; k++) {
        float cik = (k < 16) ? sx[tid*19 + 3 + k] : ov[k - 16];
        u64 a = pack2(cik, cik);
        #pragma unroll
        for (int j = 0; j < 8; j++) {
            ulonglong2 wc = W3c[k*16 + j];
            fma2(acc3[2*j],   a, wc.x, acc3[2*j]);
            fma2(acc3[2*j+1], a, wc.y, acc3[2*j+1]);
            ulonglong2 ws = W3s[k*8 + j];
            fma2(acc3[16+2*j],   a, ws.x, acc3[16+2*j]);
            fma2(acc3[16+2*j+1], a, ws.y, acc3[16+2*j+1]);
        }
    }

    // ---- relu(hc) streamed into gemm4 (64x64): 4 const + 12 smem groups -----
    u64 a4[32];
    #pragma unroll
    for (int j = 0; j < 32; j++) a4[j] = 0ull;
    #pragma unroll
    for (int q = 0; q < 32; q++) {
        float lo, hi; unpack2(acc3[q], lo, hi);
        lo = fmaxf(lo, 0.f); hi = fmaxf(hi, 0.f);
        int m = 2*q;
        u64 alo = pack2(lo, lo), ahi = pack2(hi, hi);
        #pragma unroll
        for (int j = 0; j < 4; j++) {                  // const: cols 4j..4j+3
            ulonglong2 w0 = W4c[m*16 + j];
            ulonglong2 w1 = W4c[(m+1)*16 + j];
            fma2(a4[2*j],   alo, w0.x, a4[2*j]);
            fma2(a4[2*j+1], alo, w0.y, a4[2*j+1]);
            fma2(a4[2*j],   ahi, w1.x, a4[2*j]);
            fma2(a4[2*j+1], ahi, w1.y, a4[2*j+1]);
        }
        #pragma unroll
        for (int j = 0; j < 12; j++) {                 // smem: cols 16+4j..+3
            ulonglong2 s0 = W4s[m*12 + j];
            ulonglong2 s1v = W4s[(m+1)*12 + j];
            fma2(a4[8+2*j],   alo, s0.x,  a4[8+2*j]);
            fma2(a4[8+2*j+1], alo, s0.y,  a4[8+2*j+1]);
            fma2(a4[8+2*j],   ahi, s1v.x, a4[8+2*j]);
            fma2(a4[8+2*j+1], ahi, s1v.y, a4[8+2*j+1]);
        }
    }

    // ---- relu + gemm5 (64x3, const) + sigmoid (__expf MUFU path) ------------
    float col0 = 0.f, col1 = 0.f, col2 = 0.f;
    #pragma unroll
    for (int q = 0; q < 32; q++) {
        float lo, hi; unpack2(a4[q], lo, hi);
        lo = fmaxf(lo, 0.f); hi = fmaxf(hi, 0.f);
        int m = 2*q;
        col0 += lo * CW[OFF_C3 + m*3 + 0] + hi * CW[OFF_C3 + (m+1)*3 + 0];
        col1 += lo * CW[OFF_C3 + m*3 + 1] + hi * CW[OFF_C3 + (m+1)*3 + 1];
        col2 += lo * CW[OFF_C3 + m*3 + 2] + hi * CW[OFF_C3 + (m+1)*3 + 2];
    }

    col0 = 1.f / (1.f + __expf(-col0));
    col1 = 1.f / (1.f + __expf(-col1));
    col2 = 1.f / (1.f + __expf(-col2));

    float4 r; r.x = col0; r.y = col1; r.z = col2; r.w = sigma;
    ((float4*)out)[i] = r;
}

extern "C" void kernel_launch(void* const* d_in, const int* in_sizes, int n_in,
                              void* d_out, int out_size) {
    const float* x     = (const float*)d_in[0];
    const float* grids = (const float*)d_in[1];
    const float* ws1   = (const float*)d_in[2];
    const float* ws2   = (const float*)d_in[3];
    const float* wc1   = (const float*)d_in[4];
    const float* wc2   = (const float*)d_in[5];
    const float* wc3   = (const float*)d_in[6];
    float* out = (float*)d_out;

    // pack all weights into one device buffer, then ONE memcpy node to const.
    pack_weights<<<(W_TOTAL + 255) / 256, 256>>>(ws1, ws2, wc1, wc2, wc3);
    void* wpack_ptr = nullptr;
    cudaGetSymbolAddress(&wpack_ptr, WPACK);
    cudaMemcpyToSymbolAsync(CW, wpack_ptr, W_TOTAL * sizeof(float), 0,
                            cudaMemcpyDeviceToDevice, 0);

    const int N = in_sizes[0] / 19;
    const int blocks = (N + 127) / 128;
    nerf_fused<<<blocks, 128>>>(x, grids, ws1, ws2, wc1, wc2, out, N);
}

// round 17
// speedup vs baseline: 3.2235x; 1.0651x over previous
#include <cuda_runtime.h>

typedef unsigned int u32;
typedef unsigned long long u64;

// ---- packed f32x2 helpers (Blackwell sm_103a) ------------------------------
__device__ __forceinline__ u64 pack2(float lo, float hi) {
    u64 r; asm("mov.b64 %0, {%1, %2};" : "=l"(r) : "f"(lo), "f"(hi)); return r;
}
__device__ __forceinline__ void unpack2(u64 v, float& lo, float& hi) {
    asm("mov.b64 {%0, %1}, %2;" : "=f"(lo), "=f"(hi) : "l"(v));
}
__device__ __forceinline__ void fma2(u64& d, u64 a, u64 b, u64 c) {
    asm("fma.rn.f32x2 %0, %1, %2, %3;" : "=l"(d) : "l"(a), "l"(b), "l"(c));
}

#define H2C 2654435761u
#define H3C 805459861u

// R14 port split (validated best, 792us):
//   gemm1/3: 8 const + 8 smem col-groups (cols 0..31 / 32..63)
//   gemm2:   ALL const;  gemm4: 4 const + 12 smem (cols 0..15 / 16..63)
//   gemm5:   const
// HARD RULES (earned): every LDC index compile-time/loop-index only (R8/R15);
// never force occupancy via launch_bounds caps (R4/R6/R10 spills); keep the
// gather FUSED with gemm1 and distance-1 pipelined (R13); don't add live
// state to phase A (R16).
#define OFF_S1 0
#define OFF_S2 2048
#define OFF_C1 3072
#define OFF_C2 5120
#define OFF_C3 9216
#define W_TOTAL 9408
__constant__ __align__(16) float CW[W_TOTAL];
__device__   __align__(16) float WPACK[W_TOTAL];

__global__ void pack_weights(const float* __restrict__ s1,
                             const float* __restrict__ s2,
                             const float* __restrict__ c1,
                             const float* __restrict__ c2,
                             const float* __restrict__ c3) {
    int t = blockIdx.x * 256 + threadIdx.x;
    if (t >= W_TOTAL) return;
    float v;
    if      (t < OFF_S2) v = s1[t - OFF_S1];
    else if (t < OFF_C1) v = s2[t - OFF_S2];
    else if (t < OFF_C2) v = c1[t - OFF_C1];
    else if (t < OFF_C3) v = c2[t - OFF_C2];
    else                 v = c3[t - OFF_C3];
    WPACK[t] = v;
}

// res = ceil(16 * s^l), s = float32(2^0.4) (rounded up) => 65/257/1025 at
// l=5/10/15. MAX_DIRECT = 2.
__device__ __forceinline__ void level_load(int l, float px, float py, float pz,
                                           const float* __restrict__ grids,
                                           float2* cc)
{
    const int RES_[16]  = {16,22,28,37,49,65,85,112,148,195,257,338,446,589,777,1025};
    const u32 SZ_[16]   = {4096u,10648u,21952u,50656u,117656u,274632u,
                           524288u,524288u,524288u,524288u,524288u,
                           524288u,524288u,524288u,524288u,524288u};
    const int R = RES_[l];
    const u32 S = SZ_[l];
    const float Rf = (float)R;
    int ix = (int)floorf(px * Rf);
    int iy = (int)floorf(py * Rf);
    int iz = (int)floorf(pz * Rf);

    u32 idx[8];
    if (l <= 2) {
        #pragma unroll
        for (int j = 0; j < 8; j++) {
            int cx = ix + ((j >> 2) & 1);
            int cy = iy + ((j >> 1) & 1);
            int cz = iz + (j & 1);
            idx[j] = (u32)(cz * (R * R) + cy * R + cx) % S;
        }
    } else {
        u32 hx0 = (u32)ix;           u32 hx1 = hx0 + 1u;
        u32 hy0 = (u32)iy * H2C;     u32 hy1 = hy0 + H2C;
        u32 hz0 = (u32)iz * H3C;     u32 hz1 = hz0 + H3C;
        #pragma unroll
        for (int j = 0; j < 8; j++) {
            u32 h = ((j & 4) ? hx1 : hx0) ^ ((j & 2) ? hy1 : hy0) ^ ((j & 1) ? hz1 : hz0);
            idx[j] = (l >= 6) ? (h & 524287u) : (h % S);
        }
    }

    const float2* g = (const float2*)grids + (size_t)l * 524288u;
    #pragma unroll
    for (int j = 0; j < 8; j++) cc[j] = __ldg(g + idx[j]);
}

__global__ void __launch_bounds__(128, 4) nerf_fused(
    const float* __restrict__ xin,     // (N,19)
    const float* __restrict__ grids,   // (16, 524288, 2)
    const float* __restrict__ gw_s1,   // (32,64)
    const float* __restrict__ gw_s2,   // unused (gemm2 all const)
    const float* __restrict__ gw_c1,   // (32,64)
    const float* __restrict__ gw_c2,   // (64,64)
    float* __restrict__ out,           // (N,4)
    int N)
{
    __shared__ __align__(16) ulonglong2 W1s[32 * 8];   // s1 cols 32..63
    __shared__ __align__(16) ulonglong2 W3s[32 * 8];   // c1 cols 32..63
    __shared__ __align__(16) ulonglong2 W4s[64 * 12];  // c2 cols 16..63
    __shared__ float sx[128 * 19];                     // staged xin

    const int tid = threadIdx.x;
    {
        float* w1f = (float*)W1s;
        float* w3f = (float*)W3s;
        float* w4f = (float*)W4s;
        for (int t = tid; t < 1024; t += 128) {
            int r = t >> 5, c = t & 31;
            w1f[t] = gw_s1[r * 64 + 32 + c];
            w3f[t] = gw_c1[r * 64 + 32 + c];
        }
        for (int t = tid; t < 3072; t += 128) {        // 64 rows x 48 cols (16..63)
            int r = t / 48, c = t % 48;
            w4f[t] = gw_c2[r * 64 + 16 + c];
        }
        const int base = blockIdx.x * (128 * 19);
        const int lim  = N * 19;
        #pragma unroll
        for (int t = tid; t < 128 * 19; t += 128) {
            int g = base + t;
            sx[t] = (g < lim) ? xin[g] : 0.f;
        }
    }
    __syncthreads();

    const int i = blockIdx.x * 128 + tid;
    if (i >= N) return;

    const float px = sx[tid * 19 + 0];
    const float py = sx[tid * 19 + 1];
    const float pz = sx[tid * 19 + 2];

    const int RES_[16] = {16,22,28,37,49,65,85,112,148,195,257,338,446,589,777,1025};

    // ---- phase A: gather FUSED with gemm1, distance-1 pipelined loads (R13) -
    u64 acc[32];
    #pragma unroll
    for (int j = 0; j < 32; j++) acc[j] = 0ull;
    const ulonglong2* W1c = (const ulonglong2*)(CW + OFF_S1);

    float2 ccA[8], ccB[8];
    level_load(0, px, py, pz, grids, ccA);

    #pragma unroll
    for (int l = 0; l < 16; l += 2) {
        level_load(l + 1, px, py, pz, grids, ccB);

        #pragma unroll
        for (int half = 0; half < 2; half++) {
            const int lv = l + half;
            const float2* cc = half ? ccB : ccA;

            if (half == 1 && l + 2 < 16)
                level_load(l + 2, px, py, pz, grids, ccA);

            const float Rf = (float)RES_[lv];
            float u = px * Rf, v = py * Rf, w = pz * Rf;
            float fx = u - floorf(u), fy = v - floorf(v), fz = w - floorf(w);
            const float gx = 1.f - fx, gy = 1.f - fy, gz = 1.f - fz;
            float c00x = cc[0].x*gx + cc[4].x*fx, c00y = cc[0].y*gx + cc[4].y*fx;
            float c01x = cc[1].x*gx + cc[5].x*fx, c01y = cc[1].y*gx + cc[5].y*fx;
            float c10x = cc[2].x*gx + cc[6].x*fx, c10y = cc[2].y*gx + cc[6].y*fx;
            float c11x = cc[3].x*gx + cc[7].x*fx, c11y = cc[3].y*gx + cc[7].y*fx;
            float c0x = c00x*gy + c10x*fy, c0y = c00y*gy + c10y*fy;
            float c1x = c01x*gy + c11x*fy, c1y = c01y*gy + c11y*fy;
            // NOTE: replicates reference bug: c0*(1-fz) + c1*fy  (fy, not fz!)
            float fex = c0x*gz + c1x*fy;
            float fey = c0y*gz + c1y*fy;

            u64 a0 = pack2(fex, fex);
            u64 a1 = pack2(fey, fey);
            #pragma unroll
            for (int j = 0; j < 8; j++) {
                ulonglong2 w0 = W1c[(2*lv)   * 16 + j];    // cols 4j..4j+3
                ulonglong2 w1 = W1c[(2*lv+1) * 16 + j];
                fma2(acc[2*j],   a0, w0.x, acc[2*j]);
                fma2(acc[2*j+1], a0, w0.y, acc[2*j+1]);
                fma2(acc[2*j],   a1, w1.x, acc[2*j]);
                fma2(acc[2*j+1], a1, w1.y, acc[2*j+1]);
                ulonglong2 s0 = W1s[(2*lv)   * 8 + j];     // cols 32+4j..+3
                ulonglong2 s1v = W1s[(2*lv+1) * 8 + j];
                fma2(acc[16+2*j],   a0, s0.x,  acc[16+2*j]);
                fma2(acc[16+2*j+1], a0, s0.y,  acc[16+2*j+1]);
                fma2(acc[16+2*j],   a1, s1v.x, acc[16+2*j]);
                fma2(acc[16+2*j+1], a1, s1v.y, acc[16+2*j+1]);
            }
        }
    }

    // ---- relu(h1) folded into gemm2 (64x16), ALL const ----------------------
    u64 ovacc[8];
    #pragma unroll
    for (int j = 0; j < 8; j++) ovacc[j] = 0ull;
    const ulonglong2* W2c = (const ulonglong2*)(CW + OFF_S2);

    #pragma unroll
    for (int q = 0; q < 32; q++) {
        float lo, hi; unpack2(acc[q], lo, hi);
        lo = fmaxf(lo, 0.f); hi = fmaxf(hi, 0.f);
        int m = 2*q;
        u64 alo = pack2(lo, lo), ahi = pack2(hi, hi);
        #pragma unroll
        for (int j = 0; j < 4; j++) {
            ulonglong2 w0 = W2c[m*4 + j];
            ulonglong2 w1 = W2c[(m+1)*4 + j];
            fma2(ovacc[2*j],   alo, w0.x, ovacc[2*j]);
            fma2(ovacc[2*j+1], alo, w0.y, ovacc[2*j+1]);
            fma2(ovacc[2*j],   ahi, w1.x, ovacc[2*j]);
            fma2(ovacc[2*j+1], ahi, w1.y, ovacc[2*j+1]);
        }
    }
    float ov[16];
    #pragma unroll
    for (int j = 0; j < 8; j++) unpack2(ovacc[j], ov[2*j], ov[2*j+1]);
    const float sigma = ov[0];

    // ---- gemm3 (32x64), dual-port -------------------------------------------
    u64 acc3[32];
    #pragma unroll
    for (int j = 0; j < 32; j++) acc3[j] = 0ull;
    const ulonglong2* W3c = (const ulonglong2*)(CW + OFF_C1);
    const ulonglong2* W4c = (const ulonglong2*)(CW + OFF_C2);

    #pragma unroll
    for (int k = 0; k < 32; k++) {
        float cik = (k < 16) ? sx[tid*19 + 3 + k] : ov[k - 16];
        u64 a = pack2(cik, cik);
        #pragma unroll
        for (int j = 0; j < 8; j++) {
            ulonglong2 wc = W3c[k*16 + j];
            fma2(acc3[2*j],   a, wc.x, acc3[2*j]);
            fma2(acc3[2*j+1], a, wc.y, acc3[2*j+1]);
            ulonglong2 ws = W3s[k*8 + j];
            fma2(acc3[16+2*j],   a, ws.x, acc3[16+2*j]);
            fma2(acc3[16+2*j+1], a, ws.y, acc3[16+2*j+1]);
        }
    }

    // ---- relu(hc) streamed into gemm4 (64x64): 4 const + 12 smem groups -----
    // a4[q] = out cols (2q, 2q+1): q<8 via const (cols 0..15), q>=8 via smem
    // (cols 16..63; 16+2(q-8) == 2q).
    u64 a4[32];
    #pragma unroll
    for (int j = 0; j < 32; j++) a4[j] = 0ull;
    #pragma unroll
    for (int q = 0; q < 32; q++) {
        float lo, hi; unpack2(acc3[q], lo, hi);
        lo = fmaxf(lo, 0.f); hi = fmaxf(hi, 0.f);
        int m = 2*q;
        u64 alo = pack2(lo, lo), ahi = pack2(hi, hi);
        #pragma unroll
        for (int j = 0; j < 4; j++) {                  // const: cols 4j..4j+3
            ulonglong2 w0 = W4c[m*16 + j];
            ulonglong2 w1 = W4c[(m+1)*16 + j];
            fma2(a4[2*j],   alo, w0.x, a4[2*j]);
            fma2(a4[2*j+1], alo, w0.y, a4[2*j+1]);
            fma2(a4[2*j],   ahi, w1.x, a4[2*j]);
            fma2(a4[2*j+1], ahi, w1.y, a4[2*j+1]);
        }
        #pragma unroll
        for (int j = 0; j < 12; j++) {                 // smem: cols 16+4j..+3
            ulonglong2 s0 = W4s[m*12 + j];
            ulonglong2 s1v = W4s[(m+1)*12 + j];
            fma2(a4[8+2*j],   alo, s0.x,  a4[8+2*j]);
            fma2(a4[8+2*j+1], alo, s0.y,  a4[8+2*j+1]);
            fma2(a4[8+2*j],   ahi, s1v.x, a4[8+2*j]);
            fma2(a4[8+2*j+1], ahi, s1v.y, a4[8+2*j+1]);
        }
    }

    // ---- relu + gemm5 (64x3, const) + sigmoid (__expf MUFU) -----------------
    float col0 = 0.f, col1 = 0.f, col2 = 0.f;
    #pragma unroll
    for (int q = 0; q < 32; q++) {
        float lo, hi; unpack2(a4[q], lo, hi);
        lo = fmaxf(lo, 0.f); hi = fmaxf(hi, 0.f);
        int m = 2*q;
        col0 += lo * CW[OFF_C3 + m*3 + 0] + hi * CW[OFF_C3 + (m+1)*3 + 0];
        col1 += lo * CW[OFF_C3 + m*3 + 1] + hi * CW[OFF_C3 + (m+1)*3 + 1];
        col2 += lo * CW[OFF_C3 + m*3 + 2] + hi * CW[OFF_C3 + (m+1)*3 + 2];
    }

    col0 = 1.f / (1.f + __expf(-col0));
    col1 = 1.f / (1.f + __expf(-col1));
    col2 = 1.f / (1.f + __expf(-col2));

    float4 r; r.x = col0; r.y = col1; r.z = col2; r.w = sigma;
    ((float4*)out)[i] = r;
}

extern "C" void kernel_launch(void* const* d_in, const int* in_sizes, int n_in,
                              void* d_out, int out_size) {
    const float* x     = (const float*)d_in[0];
    const float* grids = (const float*)d_in[1];
    const float* ws1   = (const float*)d_in[2];
    const float* ws2   = (const float*)d_in[3];
    const float* wc1   = (const float*)d_in[4];
    const float* wc2   = (const float*)d_in[5];
    const float* wc3   = (const float*)d_in[6];
    float* out = (float*)d_out;

    // pack all weights into one device buffer, then ONE memcpy node to const.
    pack_weights<<<(W_TOTAL + 255) / 256, 256>>>(ws1, ws2, wc1, wc2, wc3);
    void* wpack_ptr = nullptr;
    cudaGetSymbolAddress(&wpack_ptr, WPACK);
    cudaMemcpyToSymbolAsync(CW, wpack_ptr, W_TOTAL * sizeof(float), 0,
                            cudaMemcpyDeviceToDevice, 0);

    const int N = in_sizes[0] / 19;
    const int blocks = (N + 127) / 128;
    nerf_fused<<<blocks, 128>>>(x, grids, ws1, ws2, wc1, wc2, out, N);
}